// round 2
// baseline (speedup 1.0000x reference)
#include <cuda_runtime.h>
#include <cstdint>

#define B_TOTAL   131072
#define ORDER     8
#define NDIM      64
#define RANK      32
#define MID_STRIDE (RANK * NDIM * RANK)   // 65536 floats per mid core
#define ROW_STRIDE (NDIM * RANK)          // 2048 floats between r-rows

// Warp-per-element TT forward. The reference's norm-stabilization cancels
// exactly (einsum is linear in v), so the math is a plain chained matvec:
//   v <- v @ M_m[:, idx_m, :]   for each of 6 mid cores, then dot with last.
// indices may be int64 or int32 (jax x64-dependent); sniffed at runtime.
__global__ __launch_bounds__(256, 8)
void tt_forward_kernel(const int32_t* __restrict__ idx_raw,
                       const float*   __restrict__ core0,
                       const float*   __restrict__ cores_mid,
                       const float*   __restrict__ core_last,
                       float*         __restrict__ out) {
    const int warp = (blockIdx.x * blockDim.x + threadIdx.x) >> 5;
    const int lane = threadIdx.x & 31;
    if (warp >= B_TOTAL) return;

    // ---- dtype sniff: if int64, odd 32-bit words (high halves) of the first
    // 16 values are all zero (values in [0,64) are nonneg small). For int32
    // data, 16 consecutive values all being zero is ~(1/64)^16.
    uint32_t hi_or = 0;
#pragma unroll
    for (int t = 0; t < 16; t++) hi_or |= (uint32_t)idx_raw[2 * t + 1];
    const bool is64 = (hi_or == 0u);

    // ---- load this element's 8 indices (uniform across warp; L1 broadcast)
    int idx[ORDER];
    if (is64) {
        const long long* p = (const long long*)idx_raw + (long long)warp * ORDER;
#pragma unroll
        for (int j = 0; j < ORDER; j++) {
            long long t = p[j];
            t = t < 0 ? 0 : (t > NDIM - 1 ? NDIM - 1 : t);
            idx[j] = (int)t;
        }
    } else {
        const int32_t* p = idx_raw + (long long)warp * ORDER;
#pragma unroll
        for (int j = 0; j < ORDER; j++) {
            int t = p[j];
            t = t < 0 ? 0 : (t > NDIM - 1 ? NDIM - 1 : t);
            idx[j] = t;
        }
    }

    // ---- v init: row idx[0] of core0 (1, 64, 32); lane holds v[lane]
    float v = core0[idx[0] * RANK + lane];

    // ---- 6 mid cores: v_new[s] = sum_r v[r] * M[r, col, s]
#pragma unroll
    for (int m = 0; m < ORDER - 2; m++) {
        const float* M = cores_mid + m * MID_STRIDE + idx[m + 1] * RANK + lane;
        float acc = 0.0f;
#pragma unroll
        for (int r = 0; r < RANK; r++) {
            const float vr = __shfl_sync(0xffffffffu, v, r);
            acc = fmaf(vr, M[r * ROW_STRIDE], acc);
        }
        v = acc;
    }

    // ---- last core: out[b] = sum_r v[r] * core_last[r, col, 0]
    float p = v * core_last[lane * NDIM + idx[ORDER - 1]];
#pragma unroll
    for (int o = 16; o; o >>= 1) p += __shfl_xor_sync(0xffffffffu, p, o);

    if (lane == 0) out[warp] = p;
}

extern "C" void kernel_launch(void* const* d_in, const int* in_sizes, int n_in,
                              void* d_out, int out_size) {
    const int32_t* indices  = (const int32_t*)d_in[0];  // int64 or int32, sniffed
    const float*   core0    = (const float*)d_in[1];    // (1, 64, 32)
    const float*   coresmid = (const float*)d_in[2];    // (6, 32, 64, 32)
    const float*   corelast = (const float*)d_in[3];    // (32, 64, 1)
    float*         out      = (float*)d_out;            // (131072,)

    const int threads = 256;                       // 8 warps = 8 elements/block
    const int blocks  = B_TOTAL / 8;               // 16384
    tt_forward_kernel<<<blocks, threads>>>(indices, core0, coresmid, corelast, out);
}

// round 3
// speedup vs baseline: 1.1064x; 1.1064x over previous
#include <cuda_runtime.h>
#include <cstdint>

#define B_TOTAL 131072
#define NDIM 64
#define RANK 32
#define MIDS 4                       // bucketed steps S=0..3 apply cores_mid[1..4]
#define MID_STRIDE (RANK*NDIM*RANK)  // 65536
#define ROW_STRIDE (NDIM*RANK)       // 2048

// ---- scratch (static device globals; no allocation) ----
__device__ float g_vbuf[B_TOTAL * RANK];         // 16 MB ping (in-place safe)
__device__ float g_A[NDIM * NDIM * RANK];        // core0 @ M0 fold (512 KB)
__device__ float g_Z[NDIM * NDIM * RANK];        // M5 @ core_last fold (512 KB)
__device__ int   g_perm[MIDS][B_TOTAL];          // counting-sort permutations
__device__ int   g_hist[MIDS * NDIM];
__device__ int   g_offs[MIDS][NDIM + 1];
__device__ int   g_cur[MIDS * NDIM];
__device__ int   g_is64;

// ---- helpers ----
__device__ __forceinline__ int get_idx(const int32_t* raw, int e, int k, int is64) {
    int t;
    if (is64) t = (int)((const long long*)raw)[(long long)e * 8 + k];
    else      t = raw[e * 8 + k];
    return min(max(t, 0), NDIM - 1);
}
__device__ __forceinline__ unsigned long long pack2(float x, float y) {
    unsigned long long r;
    asm("mov.b64 %0,{%1,%2};" : "=l"(r) : "f"(x), "f"(y));
    return r;
}
__device__ __forceinline__ void unpack2(unsigned long long v, float& x, float& y) {
    asm("mov.b64 {%0,%1},%2;" : "=f"(x), "=f"(y) : "l"(v));
}
__device__ __forceinline__ void fma2(unsigned long long& d, unsigned long long a,
                                     unsigned long long b) {
    asm("fma.rn.f32x2 %0,%1,%2,%0;" : "+l"(d) : "l"(a), "l"(b));
}

// ---- 1) dtype sniff + zero histograms ----
__global__ void sniff_zero_kernel(const int32_t* raw) {
    int t = threadIdx.x;
    if (t < MIDS * NDIM) g_hist[t] = 0;
    if (t == 0) {
        unsigned int h = 0;
#pragma unroll
        for (int i = 0; i < 16; i++) h |= (unsigned int)raw[2 * i + 1];
        g_is64 = (h == 0u) ? 1 : 0;
    }
}

// ---- 2) histograms of idx[:, 2..5] ----
__global__ void hist_kernel(const int32_t* raw) {
    __shared__ int sh[MIDS * NDIM];
    int tid = threadIdx.x;
    sh[tid] = 0;
    __syncthreads();
    int is64 = g_is64;
    for (int e = blockIdx.x * 256 + tid; e < B_TOTAL; e += 256 * 256) {
#pragma unroll
        for (int m = 0; m < MIDS; m++) {
            int j = get_idx(raw, e, m + 2, is64);
            atomicAdd(&sh[m * NDIM + j], 1);
        }
    }
    __syncthreads();
    atomicAdd(&g_hist[tid], sh[tid]);
}

// ---- 3) exclusive scan per step (warp per step, shfl scan over 64 bins) ----
__global__ void scan_kernel() {
    int w = threadIdx.x >> 5, l = threadIdx.x & 31;
    if (w >= MIDS) return;
    int a0 = g_hist[w * NDIM + l], a1 = g_hist[w * NDIM + 32 + l];
    int s0 = a0;
#pragma unroll
    for (int o = 1; o < 32; o <<= 1) { int t = __shfl_up_sync(0xffffffffu, s0, o); if (l >= o) s0 += t; }
    int tot0 = __shfl_sync(0xffffffffu, s0, 31);
    int s1 = a1;
#pragma unroll
    for (int o = 1; o < 32; o <<= 1) { int t = __shfl_up_sync(0xffffffffu, s1, o); if (l >= o) s1 += t; }
    s1 += tot0;
    g_offs[w][l]      = s0 - a0;  g_cur[w * NDIM + l]      = s0 - a0;
    g_offs[w][32 + l] = s1 - a1;  g_cur[w * NDIM + 32 + l] = s1 - a1;
    if (l == 31) g_offs[w][NDIM] = s1;
}

// ---- 4) scatter element ids into per-step buckets ----
__global__ void scatter_kernel(const int32_t* raw) {
    int tid = threadIdx.x;
    int is64 = g_is64;
    for (int e = blockIdx.x * 256 + tid; e < B_TOTAL; e += 256 * 256) {
#pragma unroll
        for (int m = 0; m < MIDS; m++) {
            int j = get_idx(raw, e, m + 2, is64);
            int pos = atomicAdd(&g_cur[m * NDIM + j], 1);
            g_perm[m][pos] = e;
        }
    }
}

// ---- 5) precompute A[j0,j1] = core0[j0] @ M0[:,j1,:] ----
__global__ void precompA_kernel(const float* core0, const float* mids) {
    int wid = (blockIdx.x * blockDim.x + threadIdx.x) >> 5;
    int lane = threadIdx.x & 31;
    if (wid >= NDIM * NDIM) return;
    int j0 = wid >> 6, j1 = wid & 63;
    float acc = 0.0f;
#pragma unroll
    for (int r = 0; r < RANK; r++)
        acc = fmaf(core0[j0 * RANK + r], mids[r * ROW_STRIDE + j1 * RANK + lane], acc);
    g_A[wid * RANK + lane] = acc;
}

// ---- 6) precompute Z[j6,j7][r] = sum_s M5[r,j6,s] * cl[s,j7] ----
__global__ void precompZ_kernel(const float* mids, const float* cl) {
    __shared__ float sT[RANK * 33];  // sT[s*33+r] = M5[r, j6, s]
    int j6 = blockIdx.x, tid = threadIdx.x;
    const float* M5 = mids + 5 * MID_STRIDE;
    for (int i = tid; i < RANK * RANK; i += 256) {
        int r = i >> 5, s = i & 31;
        sT[s * 33 + r] = M5[r * ROW_STRIDE + j6 * RANK + s];
    }
    __syncthreads();
    int w = tid >> 5, lane = tid & 31;
    for (int j7 = w; j7 < NDIM; j7 += 8) {
        float acc = 0.0f;
#pragma unroll
        for (int s = 0; s < RANK; s++)
            acc = fmaf(cl[s * NDIM + j7], sT[s * 33 + lane], acc);
        g_Z[(j6 * NDIM + j7) * RANK + lane] = acc;
    }
}

// ---- 7) bucketed matvec step; FIRST gathers A, LAST dots with Z -> out ----
template <bool FIRST, bool LAST>
__global__ __launch_bounds__(256, 4)
void step_kernel(int S, const int32_t* raw, const float* mids, float* out) {
    __shared__ __align__(16) float slice[RANK * RANK];  // [r*32+s]
    __shared__ float stage[8][RANK * 33];
    const int tid = threadIdx.x, warp = tid >> 5, lane = tid & 31;
    const int j = blockIdx.x;
    const float* M = mids + (S + 1) * MID_STRIDE;
    for (int i = tid; i < RANK * RANK; i += 256)
        slice[i] = M[(i >> 5) * ROW_STRIDE + j * RANK + (i & 31)];
    __syncthreads();

    const int is64 = g_is64;
    const int lo = g_offs[S][j], hi = g_offs[S][j + 1];
    float* st = stage[warp];

    for (int c = blockIdx.y * 8 + warp; lo + c * 32 < hi; c += 64) {
        const int base = lo + c * 32;
        const int n = min(32, hi - base);
        int e = 0, rowidx = 0;
        if (lane < n) {
            e = g_perm[S][base + lane];
            if (FIRST)
                rowidx = get_idx(raw, e, 0, is64) * NDIM + get_idx(raw, e, 1, is64);
            else
                rowidx = e;
        }
        const float* src = FIRST ? g_A : g_vbuf;
        __syncwarp();
        for (int w = 0; w < n; w++) {
            int re = __shfl_sync(0xffffffffu, rowidx, w);
            st[w * 33 + lane] = src[re * RANK + lane];
        }
        __syncwarp();

        unsigned long long acc[16];
#pragma unroll
        for (int q = 0; q < 16; q++) acc[q] = 0ull;
#pragma unroll 8
        for (int r = 0; r < RANK; r++) {
            float vr = st[lane * 33 + r];
            unsigned long long v2 = pack2(vr, vr);
            const ulonglong2* sp = reinterpret_cast<const ulonglong2*>(slice + r * RANK);
#pragma unroll
            for (int q = 0; q < 8; q++) {
                ulonglong2 z = sp[q];
                fma2(acc[2 * q],     z.x, v2);
                fma2(acc[2 * q + 1], z.y, v2);
            }
        }

        if (!LAST) {
            __syncwarp();
#pragma unroll
            for (int q = 0; q < 16; q++) {
                float a, b;
                unpack2(acc[q], a, b);
                st[lane * 33 + 2 * q] = a;
                st[lane * 33 + 2 * q + 1] = b;
            }
            __syncwarp();
            for (int w = 0; w < n; w++) {
                int ee = __shfl_sync(0xffffffffu, e, w);
                g_vbuf[ee * RANK + lane] = st[w * 33 + lane];
            }
        } else {
            if (lane < n) {
                int zrow = get_idx(raw, e, 6, is64) * NDIM + get_idx(raw, e, 7, is64);
                const unsigned long long* zp =
                    reinterpret_cast<const unsigned long long*>(g_Z + zrow * RANK);
                unsigned long long d = 0ull;
#pragma unroll
                for (int q = 0; q < 16; q++) fma2(d, acc[q], zp[q]);
                float a, b;
                unpack2(d, a, b);
                out[e] = a + b;
            }
        }
    }
}

extern "C" void kernel_launch(void* const* d_in, const int* in_sizes, int n_in,
                              void* d_out, int out_size) {
    const int32_t* indices  = (const int32_t*)d_in[0];
    const float*   core0    = (const float*)d_in[1];
    const float*   coresmid = (const float*)d_in[2];
    const float*   corelast = (const float*)d_in[3];
    float*         out      = (float*)d_out;

    sniff_zero_kernel<<<1, 256>>>(indices);
    hist_kernel<<<256, 256>>>(indices);
    scan_kernel<<<1, 128>>>();
    scatter_kernel<<<256, 256>>>(indices);
    precompA_kernel<<<512, 256>>>(core0, coresmid);
    precompZ_kernel<<<64, 256>>>(coresmid, corelast);

    dim3 sgrid(NDIM, 8);
    step_kernel<true,  false><<<sgrid, 256>>>(0, indices, coresmid, out);
    step_kernel<false, false><<<sgrid, 256>>>(1, indices, coresmid, out);
    step_kernel<false, false><<<sgrid, 256>>>(2, indices, coresmid, out);
    step_kernel<false, true ><<<sgrid, 256>>>(3, indices, coresmid, out);
}

// round 4
// speedup vs baseline: 1.4931x; 1.3496x over previous
#include <cuda_runtime.h>
#include <cstdint>

#define B_TOTAL 131072
#define NDIM 64
#define RANK 32
#define MIDS 4                       // bucketed steps S=0..3 apply cores_mid[1..4]
#define NBLK 256                     // sort blocks; 512 elements each
#define CHUNK (B_TOTAL / NBLK)       // 512
#define MID_STRIDE (RANK*NDIM*RANK)  // 65536
#define ROW_STRIDE (NDIM*RANK)       // 2048

// ---- scratch (static device globals; no allocation) ----
__device__ float g_vbuf[B_TOTAL * RANK];         // 16 MB intermediate v
__device__ float g_A[NDIM * NDIM * RANK];        // core0 @ M0 fold (512 KB)
__device__ float g_Z[NDIM * NDIM * RANK];        // M5 @ core_last fold (512 KB)
__device__ int   g_perm[MIDS][B_TOTAL];          // counting-sort permutations
__device__ int   g_cnt[MIDS][NDIM * NBLK];       // per-block counts -> scanned offsets
__device__ int   g_offs[MIDS][NDIM + 1];         // bin boundaries

// ---- helpers ----
__device__ __forceinline__ int sniff64(const int32_t* raw) {
    unsigned int h = 0;
#pragma unroll
    for (int i = 0; i < 16; i++) h |= (unsigned int)raw[2 * i + 1];
    return (h == 0u) ? 1 : 0;
}
__device__ __forceinline__ int get_idx(const int32_t* raw, int e, int k, int is64) {
    int t;
    if (is64) t = (int)((const long long*)raw)[(long long)e * 8 + k];
    else      t = raw[e * 8 + k];
    return min(max(t, 0), NDIM - 1);
}
__device__ __forceinline__ unsigned long long pack2(float x, float y) {
    unsigned long long r;
    asm("mov.b64 %0,{%1,%2};" : "=l"(r) : "f"(x), "f"(y));
    return r;
}
__device__ __forceinline__ void unpack2(unsigned long long v, float& x, float& y) {
    asm("mov.b64 {%0,%1},%2;" : "=f"(x), "=f"(y) : "l"(v));
}
__device__ __forceinline__ void fma2(unsigned long long& d, unsigned long long a,
                                     unsigned long long b) {
    asm("fma.rn.f32x2 %0,%1,%2,%0;" : "+l"(d) : "l"(a), "l"(b));
}

// ---- 1) per-block histograms (smem only; no global atomics) ----
__global__ __launch_bounds__(256)
void blockhist_kernel(const int32_t* __restrict__ raw) {
    __shared__ int cnt[MIDS * NDIM];
    const int tid = threadIdx.x, b = blockIdx.x;
    cnt[tid] = 0;
    __syncthreads();
    const int is64 = sniff64(raw);
    const int base = b * CHUNK;
#pragma unroll
    for (int i = 0; i < CHUNK / 256; i++) {
        const int e = base + i * 256 + tid;
#pragma unroll
        for (int m = 0; m < MIDS; m++) {
            int j = get_idx(raw, e, m + 2, is64);
            atomicAdd(&cnt[m * NDIM + j], 1);
        }
    }
    __syncthreads();
    // tid -> (m = tid/64, j = tid%64)
    g_cnt[tid >> 6][(tid & 63) * NBLK + b] = cnt[tid];
}

// ---- 2) exclusive scan of 16384 (j,block) counts per step ----
__global__ __launch_bounds__(1024)
void scan_kernel() {
    __shared__ int sh[1024];
    const int m = blockIdx.x, t = threadIdx.x;
    int vals[16], s = 0;
#pragma unroll
    for (int i = 0; i < 16; i++) { vals[i] = g_cnt[m][t * 16 + i]; s += vals[i]; }
    sh[t] = s;
    __syncthreads();
    for (int off = 1; off < 1024; off <<= 1) {
        int v = (t >= off) ? sh[t - off] : 0;
        __syncthreads();
        sh[t] += v;
        __syncthreads();
    }
    int run = sh[t] - s;  // exclusive prefix of this thread's chunk
#pragma unroll
    for (int i = 0; i < 16; i++) {
        int f = t * 16 + i;
        g_cnt[m][f] = run;                       // in-place: now = global offset
        if ((f & (NBLK - 1)) == 0) g_offs[m][f >> 8] = run;  // bin boundary (b==0)
        run += vals[i];
    }
    if (t == 1023) g_offs[m][NDIM] = B_TOTAL;
}

// ---- 3) scatter: smem-ranked, precomputed per-block bases ----
__global__ __launch_bounds__(256)
void scatter_kernel(const int32_t* __restrict__ raw) {
    __shared__ int sbase[MIDS * NDIM];
    __shared__ int cur[MIDS * NDIM];
    const int tid = threadIdx.x, b = blockIdx.x;
    sbase[tid] = g_cnt[tid >> 6][(tid & 63) * NBLK + b];
    cur[tid] = 0;
    __syncthreads();
    const int is64 = sniff64(raw);
    const int base = b * CHUNK;
#pragma unroll
    for (int i = 0; i < CHUNK / 256; i++) {
        const int e = base + i * 256 + tid;
#pragma unroll
        for (int m = 0; m < MIDS; m++) {
            int j = get_idx(raw, e, m + 2, is64);
            int local = atomicAdd(&cur[m * NDIM + j], 1);
            g_perm[m][sbase[m * NDIM + j] + local] = e;
        }
    }
}

// ---- 4) precompute A and Z (merged) ----
__global__ __launch_bounds__(256)
void precomp_kernel(const float* __restrict__ core0,
                    const float* __restrict__ mids,
                    const float* __restrict__ cl) {
    const int tid = threadIdx.x;
    if (blockIdx.x < 512) {
        // A[j0,j1] = core0[j0] @ M0[:,j1,:]
        int wid = blockIdx.x * 8 + (tid >> 5);
        int lane = tid & 31;
        int j0 = wid >> 6, j1 = wid & 63;
        float acc = 0.0f;
#pragma unroll
        for (int r = 0; r < RANK; r++)
            acc = fmaf(core0[j0 * RANK + r], mids[r * ROW_STRIDE + j1 * RANK + lane], acc);
        g_A[wid * RANK + lane] = acc;
    } else {
        // Z[j6,j7][r] = sum_s M5[r,j6,s] * cl[s,j7]
        __shared__ float sT[RANK * 33];
        int j6 = blockIdx.x - 512;
        const float* M5 = mids + 5 * MID_STRIDE;
        for (int i = tid; i < RANK * RANK; i += 256) {
            int r = i >> 5, s = i & 31;
            sT[s * 33 + r] = M5[r * ROW_STRIDE + j6 * RANK + s];
        }
        __syncthreads();
        int w = tid >> 5, lane = tid & 31;
        for (int j7 = w; j7 < NDIM; j7 += 8) {
            float acc = 0.0f;
#pragma unroll
            for (int s = 0; s < RANK; s++)
                acc = fmaf(cl[s * NDIM + j7], sT[s * 33 + lane], acc);
            g_Z[(j6 * NDIM + j7) * RANK + lane] = acc;
        }
    }
}

// ---- 5) bucketed matvec step; FIRST gathers A, LAST dots with Z -> out ----
template <bool FIRST, bool LAST>
__global__ __launch_bounds__(256, 4)
void step_kernel(int S, const int32_t* __restrict__ raw,
                 const float* __restrict__ mids, float* __restrict__ out) {
    __shared__ __align__(16) float slice[RANK * RANK];  // [r*32+s]
    __shared__ float stage[8][RANK * 33];
    const int tid = threadIdx.x, warp = tid >> 5, lane = tid & 31;
    const int j = blockIdx.x;
    const float* M = mids + (S + 1) * MID_STRIDE;
    for (int i = tid; i < RANK * RANK; i += 256)
        slice[i] = M[(i >> 5) * ROW_STRIDE + j * RANK + (i & 31)];
    __syncthreads();

    const int is64 = sniff64(raw);
    const int lo = g_offs[S][j], hi = g_offs[S][j + 1];
    float* st = stage[warp];

    for (int c = blockIdx.y * 8 + warp; lo + c * 32 < hi; c += 64) {
        const int base = lo + c * 32;
        const int n = min(32, hi - base);
        int e = 0, rowidx = 0;
        if (lane < n) {
            e = g_perm[S][base + lane];
            if (FIRST)
                rowidx = get_idx(raw, e, 0, is64) * NDIM + get_idx(raw, e, 1, is64);
            else
                rowidx = e;
        }
        const float* src = FIRST ? g_A : g_vbuf;
        __syncwarp();
        for (int w = 0; w < n; w++) {
            int re = __shfl_sync(0xffffffffu, rowidx, w);
            st[w * 33 + lane] = src[re * RANK + lane];
        }
        __syncwarp();

        unsigned long long acc[16];
#pragma unroll
        for (int q = 0; q < 16; q++) acc[q] = 0ull;
#pragma unroll 8
        for (int r = 0; r < RANK; r++) {
            float vr = st[lane * 33 + r];
            unsigned long long v2 = pack2(vr, vr);
            const ulonglong2* sp = reinterpret_cast<const ulonglong2*>(slice + r * RANK);
#pragma unroll
            for (int q = 0; q < 8; q++) {
                ulonglong2 z = sp[q];
                fma2(acc[2 * q],     z.x, v2);
                fma2(acc[2 * q + 1], z.y, v2);
            }
        }

        if (!LAST) {
            __syncwarp();
#pragma unroll
            for (int q = 0; q < 16; q++) {
                float a, b;
                unpack2(acc[q], a, b);
                st[lane * 33 + 2 * q] = a;
                st[lane * 33 + 2 * q + 1] = b;
            }
            __syncwarp();
            for (int w = 0; w < n; w++) {
                int ee = __shfl_sync(0xffffffffu, e, w);
                g_vbuf[ee * RANK + lane] = st[w * 33 + lane];
            }
        } else {
            if (lane < n) {
                int zrow = get_idx(raw, e, 6, is64) * NDIM + get_idx(raw, e, 7, is64);
                const unsigned long long* zp =
                    reinterpret_cast<const unsigned long long*>(g_Z + zrow * RANK);
                unsigned long long d = 0ull;
#pragma unroll
                for (int q = 0; q < 16; q++) fma2(d, acc[q], zp[q]);
                float a, b;
                unpack2(d, a, b);
                out[e] = a + b;
            }
        }
    }
}

extern "C" void kernel_launch(void* const* d_in, const int* in_sizes, int n_in,
                              void* d_out, int out_size) {
    const int32_t* indices  = (const int32_t*)d_in[0];
    const float*   core0    = (const float*)d_in[1];
    const float*   coresmid = (const float*)d_in[2];
    const float*   corelast = (const float*)d_in[3];
    float*         out      = (float*)d_out;

    blockhist_kernel<<<NBLK, 256>>>(indices);
    scan_kernel<<<MIDS, 1024>>>();
    scatter_kernel<<<NBLK, 256>>>(indices);
    precomp_kernel<<<512 + 64, 256>>>(core0, coresmid, corelast);

    dim3 sgrid(NDIM, 8);
    step_kernel<true,  false><<<sgrid, 256>>>(0, indices, coresmid, out);
    step_kernel<false, false><<<sgrid, 256>>>(1, indices, coresmid, out);
    step_kernel<false, false><<<sgrid, 256>>>(2, indices, coresmid, out);
    step_kernel<false, true ><<<sgrid, 256>>>(3, indices, coresmid, out);
}

// round 5
// speedup vs baseline: 2.1597x; 1.4464x over previous
#include <cuda_runtime.h>
#include <cstdint>

#define B_TOTAL 131072
#define NDIM 64
#define RANK 32
#define NPAIR (NDIM * NDIM)            // 4096 bins per step
#define MID_STRIDE (RANK*NDIM*RANK)    // 65536
#define ROW_STRIDE (NDIM*RANK)         // 2048

typedef unsigned long long ull;

// ---- scratch (static device globals; zero-initialized at load) ----
__device__ float g_vbuf[B_TOTAL * RANK];     // 16 MB intermediate v
__device__ float g_A[NPAIR * RANK];          // (core0@M0)[j0,j1] rows   (512 KB)
__device__ float g_Z[NPAIR * RANK];          // (M5@last)[j6,j7] rows    (512 KB)
__device__ float g_P1[NPAIR * RANK * RANK];  // M1@M2 pair fold (16 MB)
__device__ float g_P2[NPAIR * RANK * RANK];  // M3@M4 pair fold (16 MB)
__device__ int   g_perm[2][B_TOTAL];
__device__ int   g_hist[2][NPAIR];           // zeroed by scan for next replay
__device__ int   g_base[2][NPAIR + 1];
__device__ int   g_cur[2][NPAIR];

// ---- helpers ----
__device__ __forceinline__ int sniff64(const int32_t* raw) {
    unsigned int h = 0;
#pragma unroll
    for (int i = 0; i < 16; i++) h |= (unsigned int)raw[2 * i + 1];
    return (h == 0u) ? 1 : 0;
}
__device__ __forceinline__ int get_idx(const int32_t* raw, int e, int k, int is64) {
    int t;
    if (is64) t = (int)((const long long*)raw)[(long long)e * 8 + k];
    else      t = raw[e * 8 + k];
    return min(max(t, 0), NDIM - 1);
}
__device__ __forceinline__ ull pack2(float x, float y) {
    ull r; asm("mov.b64 %0,{%1,%2};" : "=l"(r) : "f"(x), "f"(y)); return r;
}
__device__ __forceinline__ void unpack2(ull v, float& x, float& y) {
    asm("mov.b64 {%0,%1},%2;" : "=f"(x), "=f"(y) : "l"(v));
}
__device__ __forceinline__ void fma2(ull& d, ull a, ull b) {
    asm("fma.rn.f32x2 %0,%1,%2,%0;" : "+l"(d) : "l"(a), "l"(b));
}

// ============================================================================
// K1: histogram + A + Z + P1 + P2 (all independent; one launch)
//   blocks [0,64)      : histogram (global spread atomics)
//   blocks [64,128)    : A[j0,j1]  = core0[j0] @ M0[:,j1,:]
//   blocks [128,192)   : Z[j6,j7][r] = sum_s M5[r,j6,s]*last[s,j7]
//   blocks [192,704)   : P1 fold (M1,M2)
//   blocks [704,1216)  : P2 fold (M3,M4)
// ============================================================================
__global__ __launch_bounds__(256)
void k1_prep(const int32_t* __restrict__ raw,
             const float* __restrict__ core0,
             const float* __restrict__ mids,
             const float* __restrict__ cl) {
    __shared__ float S[RANK * 34];   // reused: fold slice^T / Z transpose
    const int b = blockIdx.x, tid = threadIdx.x;
    const int warp = tid >> 5, lane = tid & 31;

    if (b < 64) {
        // ---- histogram of pair keys ----
        const int is64 = sniff64(raw);
#pragma unroll
        for (int i = 0; i < 8; i++) {
            const int e = b * 2048 + i * 256 + tid;
            int k0 = get_idx(raw, e, 2, is64) * NDIM + get_idx(raw, e, 3, is64);
            int k1 = get_idx(raw, e, 4, is64) * NDIM + get_idx(raw, e, 5, is64);
            atomicAdd(&g_hist[0][k0], 1);
            atomicAdd(&g_hist[1][k1], 1);
        }
    } else if (b < 128) {
        // ---- A: j0 = b-64; warp covers 8 j1 values ----
        const int j0 = b - 64;
        if (tid < RANK) S[tid] = core0[j0 * RANK + tid];
        __syncthreads();
#pragma unroll
        for (int t = 0; t < 8; t++) {
            const int j1 = warp * 8 + t;
            float acc = 0.0f;
#pragma unroll
            for (int r = 0; r < RANK; r++)
                acc = fmaf(S[r], mids[r * ROW_STRIDE + j1 * RANK + lane], acc);
            g_A[(j0 * NDIM + j1) * RANK + lane] = acc;
        }
    } else if (b < 192) {
        // ---- Z: j6 = b-128 ----
        const int j6 = b - 128;
        const float* M5 = mids + 5 * MID_STRIDE;
        for (int i = tid; i < RANK * RANK; i += 256) {
            int r = i >> 5, s = i & 31;
            S[s * 34 + r] = M5[r * ROW_STRIDE + j6 * RANK + s];  // S[s][r]
        }
        __syncthreads();
#pragma unroll
        for (int t = 0; t < 8; t++) {
            const int j7 = warp * 8 + t;
            float acc = 0.0f;
#pragma unroll
            for (int s = 0; s < RANK; s++)
                acc = fmaf(cl[s * NDIM + j7], S[s * 34 + lane], acc);
            g_Z[(j6 * NDIM + j7) * RANK + lane] = acc;
        }
    } else {
        // ---- pair folds: P[j_a,j_b][r][s] = sum_m Ma[r,j_a,m] * Mb[m,j_b,s] ----
        const int which = (b < 704) ? 0 : 1;               // 0 -> P1, 1 -> P2
        const int x = b - (which ? 704 : 192);             // 0..511
        const int ja = x >> 3;
        const float* Ma = mids + (which ? 3 : 1) * MID_STRIDE;
        const float* Mb = mids + (which ? 4 : 2) * MID_STRIDE;
        float* P = which ? g_P2 : g_P1;

        // S[m*34 + r] = Ma[r, ja, m]   (transposed, r-pairs adjacent)
        for (int i = tid; i < RANK * RANK; i += 256) {
            int r = i >> 5, m = i & 31;
            S[m * 34 + r] = Ma[r * ROW_STRIDE + ja * RANK + m];
        }
        __syncthreads();

        const int jb = (x & 7) * 8 + warp;                 // one j3/j5 per warp
        float m2[RANK];
#pragma unroll
        for (int m = 0; m < RANK; m++)
            m2[m] = Mb[m * ROW_STRIDE + jb * RANK + lane];

        ull acc2[16];
#pragma unroll
        for (int q = 0; q < 16; q++) acc2[q] = 0ull;
#pragma unroll
        for (int m = 0; m < RANK; m++) {
            const ull dup = pack2(m2[m], m2[m]);
            const ull* Sp = reinterpret_cast<const ull*>(S + m * 34);
#pragma unroll
            for (int rp = 0; rp < 16; rp++) fma2(acc2[rp], Sp[rp], dup);
        }
        float* Pp = P + (ja * NDIM + jb) * (RANK * RANK);
#pragma unroll
        for (int rp = 0; rp < 16; rp++) {
            float a, c;
            unpack2(acc2[rp], a, c);
            Pp[(2 * rp) * RANK + lane]     = a;
            Pp[(2 * rp + 1) * RANK + lane] = c;
        }
    }
}

// ============================================================================
// K2: exclusive scan of 4096 bins per step; init g_cur; reset g_hist
// ============================================================================
__global__ __launch_bounds__(1024)
void k2_scan() {
    __shared__ int sh[1024];
    const int m = blockIdx.x, t = threadIdx.x;
    int4 v4 = reinterpret_cast<const int4*>(g_hist[m])[t];
    int vals[4] = {v4.x, v4.y, v4.z, v4.w};
    int s = vals[0] + vals[1] + vals[2] + vals[3];
    sh[t] = s;
    __syncthreads();
    for (int off = 1; off < 1024; off <<= 1) {
        int u = (t >= off) ? sh[t - off] : 0;
        __syncthreads();
        sh[t] += u;
        __syncthreads();
    }
    int run = sh[t] - s;
#pragma unroll
    for (int i = 0; i < 4; i++) {
        int bin = t * 4 + i;
        g_base[m][bin] = run;
        g_cur[m][bin]  = run;
        g_hist[m][bin] = 0;        // ready for next graph replay
        run += vals[i];
    }
    if (t == 1023) g_base[m][NPAIR] = B_TOTAL;
}

// ============================================================================
// K3: scatter via spread global atomics (4096 cursors per step)
// ============================================================================
__global__ __launch_bounds__(256)
void k3_scatter(const int32_t* __restrict__ raw) {
    const int is64 = sniff64(raw);
    for (int e = blockIdx.x * 256 + threadIdx.x; e < B_TOTAL; e += gridDim.x * 256) {
        int k0 = get_idx(raw, e, 2, is64) * NDIM + get_idx(raw, e, 3, is64);
        int k1 = get_idx(raw, e, 4, is64) * NDIM + get_idx(raw, e, 5, is64);
        g_perm[0][atomicAdd(&g_cur[0][k0], 1)] = e;
        g_perm[1][atomicAdd(&g_cur[1][k1], 1)] = e;
    }
}

// ============================================================================
// K4/K5: bucketed matvec. One warp per bin (4096 bins, ~32 elems each).
//   FIRST: v_in gathered from A by (j0,j1); else from g_vbuf by element.
//   LAST:  dot with Z[(j6,j7)] -> out;   else write g_vbuf.
// ============================================================================
template <bool FIRST, bool LAST>
__global__ __launch_bounds__(32)
void step_kernel(int S, const int32_t* __restrict__ raw,
                 const float* __restrict__ Ptab, float* __restrict__ out) {
    __shared__ __align__(16) float slice[RANK * RANK];
    __shared__ float st[RANK * 33];
    const int lane = threadIdx.x;
    const int bin = blockIdx.x;
    const int lo = g_base[S][bin], hi = g_base[S][bin + 1];
    if (lo == hi) return;

    // contiguous 4 KB slice load
    const float4* src4 = reinterpret_cast<const float4*>(Ptab + bin * (RANK * RANK));
    float4* dst4 = reinterpret_cast<float4*>(slice);
#pragma unroll
    for (int i = 0; i < 8; i++) dst4[i * 32 + lane] = src4[i * 32 + lane];

    const int is64 = (FIRST || LAST) ? sniff64(raw) : 0;
    __syncwarp();

    for (int base = lo; base < hi; base += 32) {
        const int n = min(32, hi - base);
        int e = 0, rowidx = 0;
        if (lane < n) {
            e = g_perm[S][base + lane];
            rowidx = FIRST ? (get_idx(raw, e, 0, is64) * NDIM + get_idx(raw, e, 1, is64))
                           : e;
        }
        const float* src = FIRST ? g_A : g_vbuf;
        __syncwarp();
        for (int w = 0; w < n; w++) {
            int re = __shfl_sync(0xffffffffu, rowidx, w);
            st[w * 33 + lane] = src[re * RANK + lane];
        }
        __syncwarp();

        ull acc[16];
#pragma unroll
        for (int q = 0; q < 16; q++) acc[q] = 0ull;
#pragma unroll 8
        for (int r = 0; r < RANK; r++) {
            float vr = st[lane * 33 + r];
            ull v2 = pack2(vr, vr);
            const ulonglong2* sp = reinterpret_cast<const ulonglong2*>(slice + r * RANK);
#pragma unroll
            for (int q = 0; q < 8; q++) {
                ulonglong2 z = sp[q];
                fma2(acc[2 * q],     z.x, v2);
                fma2(acc[2 * q + 1], z.y, v2);
            }
        }

        if (!LAST) {
            __syncwarp();
#pragma unroll
            for (int q = 0; q < 16; q++) {
                float a, c;
                unpack2(acc[q], a, c);
                st[lane * 33 + 2 * q]     = a;
                st[lane * 33 + 2 * q + 1] = c;
            }
            __syncwarp();
            for (int w = 0; w < n; w++) {
                int ee = __shfl_sync(0xffffffffu, e, w);
                g_vbuf[ee * RANK + lane] = st[w * 33 + lane];
            }
        } else {
            if (lane < n) {
                int zrow = get_idx(raw, e, 6, is64) * NDIM + get_idx(raw, e, 7, is64);
                const ull* zp = reinterpret_cast<const ull*>(g_Z + zrow * RANK);
                ull d = 0ull;
#pragma unroll
                for (int q = 0; q < 16; q++) fma2(d, acc[q], zp[q]);
                float a, c;
                unpack2(d, a, c);
                out[e] = a + c;
            }
        }
    }
}

extern "C" void kernel_launch(void* const* d_in, const int* in_sizes, int n_in,
                              void* d_out, int out_size) {
    const int32_t* indices  = (const int32_t*)d_in[0];
    const float*   core0    = (const float*)d_in[1];
    const float*   coresmid = (const float*)d_in[2];
    const float*   corelast = (const float*)d_in[3];
    float*         out      = (float*)d_out;

    k1_prep<<<1216, 256>>>(indices, core0, coresmid, corelast);
    k2_scan<<<2, 1024>>>();
    k3_scatter<<<128, 256>>>(indices);

    float* p1;  cudaGetSymbolAddress((void**)&p1, g_P1);
    float* p2;  cudaGetSymbolAddress((void**)&p2, g_P2);
    step_kernel<true,  false><<<NPAIR, 32>>>(0, indices, p1, out);
    step_kernel<false, true ><<<NPAIR, 32>>>(1, indices, p2, out);
}